// round 4
// baseline (speedup 1.0000x reference)
#include <cuda_runtime.h>
#include <cuda_bf16.h>
#include <cstdint>

#define D        64
#define TE       128
#define THREADS  256

#define SWZ(o) ((o) ^ (((o) >> 3) & 0x70))

// Pre-split, per-lane-fragment-ordered weights: [r][kblk][nblk][lane] = {bh0,bh1,bl0,bl1}
__device__ uint4 g_Wfrag[8][4][8][32];

static __device__ __forceinline__ uint32_t pack_bf16(float lo, float hi) {
    __nv_bfloat162 v = __floats2bfloat162_rn(lo, hi);
    return *reinterpret_cast<uint32_t*>(&v);
}

__global__ void prep_w(const float* __restrict__ W) {
    const int r    = blockIdx.x;
    const int t    = threadIdx.x;          // 1024 threads
    const int kblk = t >> 8;
    const int nblk = (t >> 5) & 7;
    const int lane = t & 31;

    const int n  = nblk * 8 + (lane >> 2);
    const int t2 = (lane & 3) * 2;
    const int k0 = kblk * 16;

    float w[4];
    w[0] = W[((size_t)r * D + k0 + t2    ) * D + n];
    w[1] = W[((size_t)r * D + k0 + t2 + 1) * D + n];
    w[2] = W[((size_t)r * D + k0 + t2 + 8) * D + n];
    w[3] = W[((size_t)r * D + k0 + t2 + 9) * D + n];

    float h[4], l[4];
    #pragma unroll
    for (int i = 0; i < 4; i++) {
        h[i] = __bfloat162float(__float2bfloat16(w[i]));
        l[i] = w[i] - h[i];
    }
    g_Wfrag[r][kblk][nblk][lane] =
        make_uint4(pack_bf16(h[0], h[1]), pack_bf16(h[2], h[3]),
                   pack_bf16(l[0], l[1]), pack_bf16(l[2], l[3]));
}

static __device__ __forceinline__ uint32_t smem_u32(const void* p) {
    uint32_t a;
    asm("{ .reg .u64 t; cvta.to.shared.u64 t, %1; cvt.u32.u64 %0, t; }" : "=r"(a) : "l"(p));
    return a;
}

#define LDMATRIX_X4(fr, addr)                                              \
    asm volatile("ldmatrix.sync.aligned.m8n8.x4.shared.b16 "               \
                 "{%0, %1, %2, %3}, [%4];"                                 \
                 : "=r"((fr)[0]), "=r"((fr)[1]), "=r"((fr)[2]), "=r"((fr)[3]) \
                 : "r"(addr))

#define MMA_BF16(acc, a, b0, b1)                                           \
    asm volatile("mma.sync.aligned.m16n8k16.row.col.f32.bf16.bf16.f32 "    \
                 "{%0, %1, %2, %3}, {%4, %5, %6, %7}, {%8, %9}, "          \
                 "{%0, %1, %2, %3};"                                       \
                 : "+f"((acc)[0]), "+f"((acc)[1]), "+f"((acc)[2]), "+f"((acc)[3]) \
                 : "r"((a)[0]), "r"((a)[1]), "r"((a)[2]), "r"((a)[3]),     \
                   "r"(b0), "r"(b1))

__global__ __launch_bounds__(THREADS, 3)
void rgcn_hmma_kernel(const float* __restrict__ feat,
                      const int*   __restrict__ edge_src,
                      const int*   __restrict__ edge_dst,
                      float*       __restrict__ out,
                      int E)
{
    __shared__ __align__(1024) __nv_bfloat16 Ah[TE * D];   // 16KB, SW128-swizzled
    __shared__ __align__(1024) __nv_bfloat16 Al[TE * D];   // 16KB

    const int r   = blockIdx.y;
    const int e0  = blockIdx.x * TE;
    const int tid = threadIdx.x;
    const int wid = tid >> 5;      // warp owns edges [wid*16, wid*16+16), all 64 cols
    const int lid = tid & 31;
    const int nE  = min(TE, E - e0);

    char* Ahb = reinterpret_cast<char*>(Ah);
    char* Alb = reinterpret_cast<char*>(Al);

    // ---- gather + bf16 hi/lo split into swizzled smem ----
    {
        const int e    = tid >> 1;
        const int half = tid & 1;
        if (e < nE) {
            const int s = edge_src[(size_t)r * E + e0 + e];
            const float4* fr = reinterpret_cast<const float4*>(feat + (size_t)s * D);
            #pragma unroll
            for (int qp = 0; qp < 8; qp++) {
                const float4 v = fr[2 * qp + half];
                float h0 = __bfloat162float(__float2bfloat16(v.x));
                float h1 = __bfloat162float(__float2bfloat16(v.y));
                float h2 = __bfloat162float(__float2bfloat16(v.z));
                float h3 = __bfloat162float(__float2bfloat16(v.w));
                const uint32_t o = SWZ((uint32_t)(e * 128 + qp * 16 + half * 8));
                *reinterpret_cast<uint2*>(Ahb + o) =
                    make_uint2(pack_bf16(h0, h1), pack_bf16(h2, h3));
                *reinterpret_cast<uint2*>(Alb + o) =
                    make_uint2(pack_bf16(v.x - h0, v.y - h1),
                               pack_bf16(v.z - h2, v.w - h3));
            }
        } else {
            #pragma unroll
            for (int qp = 0; qp < 8; qp++) {
                const uint32_t o = SWZ((uint32_t)(e * 128 + qp * 16 + half * 8));
                *reinterpret_cast<uint2*>(Ahb + o) = make_uint2(0u, 0u);
                *reinterpret_cast<uint2*>(Alb + o) = make_uint2(0u, 0u);
            }
        }
    }
    __syncthreads();

    // ---- HMMA mainloop: one m16 slice per warp, 8 n-blocks, D = Ah*Bh + Al*Bh + Ah*Bl
    float acc[8][4];
    #pragma unroll
    for (int nb = 0; nb < 8; nb++)
        #pragma unroll
        for (int j = 0; j < 4; j++) acc[nb][j] = 0.f;

    const uint32_t ah_base = smem_u32(Ah);
    const uint32_t al_base = smem_u32(Al);
    const int lrow = lid & 15;
    const int lkof = (lid >> 4) * 16;

    #pragma unroll
    for (int kblk = 0; kblk < 4; kblk++) {
        uint32_t afh[4], afl[4];
        const int row = wid * 16 + lrow;
        const uint32_t off = SWZ((uint32_t)(row * 128 + kblk * 32 + lkof));
        LDMATRIX_X4(afh, ah_base + off);
        LDMATRIX_X4(afl, al_base + off);

        #pragma unroll
        for (int nb = 0; nb < 8; nb++) {
            const uint4 B = g_Wfrag[r][kblk][nb][lid];
            MMA_BF16(acc[nb], afh, B.x, B.y);
            MMA_BF16(acc[nb], afl, B.x, B.y);
            MMA_BF16(acc[nb], afh, B.z, B.w);
        }
    }

    // ---- scatter: pair-shuffle into 16B runs; each 4-lane quad covers one
    //      contiguous 64B span of a single edge's output row (coalesced REDG)
    const int g = lid >> 2;
    int  dn[2];
    bool ok[2];
    #pragma unroll
    for (int rh = 0; rh < 2; rh++) {
        const int el = wid * 16 + rh * 8 + g;
        ok[rh] = (el < nE);
        dn[rh] = ok[rh] ? edge_dst[(size_t)r * E + e0 + el] : 0;
    }

    const int odd     = lid & 1;
    const int colquad = ((lid & 2) >> 1) * 4;      // 0 or 4 within n8 block

    #pragma unroll
    for (int rh = 0; rh < 2; rh++) {
        #pragma unroll
        for (int nbp = 0; nbp < 4; nbp++) {
            // even lane emits nb = nbp*2, odd emits nbp*2+1;
            // each sends the partner's nb, receives its missing half.
            const float s0 = odd ? acc[nbp * 2][rh * 2]     : acc[nbp * 2 + 1][rh * 2];
            const float s1 = odd ? acc[nbp * 2][rh * 2 + 1] : acc[nbp * 2 + 1][rh * 2 + 1];
            const float m0 = odd ? acc[nbp * 2 + 1][rh * 2]     : acc[nbp * 2][rh * 2];
            const float m1 = odd ? acc[nbp * 2 + 1][rh * 2 + 1] : acc[nbp * 2][rh * 2 + 1];
            const float r0 = __shfl_xor_sync(0xffffffffu, s0, 1);
            const float r1 = __shfl_xor_sync(0xffffffffu, s1, 1);

            const float v0 = odd ? r0 : m0;
            const float v1 = odd ? r1 : m1;
            const float v2 = odd ? m0 : r0;
            const float v3 = odd ? m1 : r1;

            if (ok[rh]) {
                const int col = (nbp * 2 + odd) * 8 + colquad;   // quad covers 16 consecutive floats
                float* o = out + (size_t)dn[rh] * D + col;       // 16B aligned
                asm volatile("red.global.add.v4.f32 [%0], {%1, %2, %3, %4};"
                             :: "l"(o), "f"(v0), "f"(v1), "f"(v2), "f"(v3)
                             : "memory");
            }
        }
    }
}

extern "C" void kernel_launch(void* const* d_in, const int* in_sizes, int n_in,
                              void* d_out, int out_size)
{
    const float* feat     = (const float*)d_in[0];
    const float* weight   = (const float*)d_in[1];
    const int*   edge_src = (const int*)d_in[2];
    const int*   edge_dst = (const int*)d_in[3];
    float*       out      = (float*)d_out;

    const int R = in_sizes[1] / (D * D);     // 8
    const int E = in_sizes[2] / R;           // 100000

    cudaMemsetAsync(d_out, 0, (size_t)out_size * sizeof(float), 0);

    prep_w<<<R, 1024>>>(weight);

    dim3 grid((E + TE - 1) / TE, R);
    rgcn_hmma_kernel<<<grid, THREADS>>>(feat, edge_src, edge_dst, out, E);
}

// round 5
// speedup vs baseline: 1.0656x; 1.0656x over previous
#include <cuda_runtime.h>
#include <cuda_bf16.h>
#include <cstdint>

#define D        64
#define TE       128
#define THREADS  256

#define SWZ(o) ((o) ^ (((o) >> 3) & 0x70))

// Pre-split, per-lane-fragment-ordered weights: [r][kblk][nblk][lane] = {bh0,bh1,bl0,bl1}
__device__ uint4 g_Wfrag[8][4][8][32];

static __device__ __forceinline__ uint32_t pack_bf16(float lo, float hi) {
    __nv_bfloat162 v = __floats2bfloat162_rn(lo, hi);   // .x = lo (low 16 bits)
    return *reinterpret_cast<uint32_t*>(&v);
}

__global__ void prep_w(const float* __restrict__ W) {
    const int r    = blockIdx.x;
    const int t    = threadIdx.x;          // 1024 threads
    const int kblk = t >> 8;
    const int nblk = (t >> 5) & 7;
    const int lane = t & 31;

    const int n  = nblk * 8 + (lane >> 2);
    const int t2 = (lane & 3) * 2;
    const int k0 = kblk * 16;

    float w[4];
    w[0] = W[((size_t)r * D + k0 + t2    ) * D + n];
    w[1] = W[((size_t)r * D + k0 + t2 + 1) * D + n];
    w[2] = W[((size_t)r * D + k0 + t2 + 8) * D + n];
    w[3] = W[((size_t)r * D + k0 + t2 + 9) * D + n];

    float h[4], l[4];
    #pragma unroll
    for (int i = 0; i < 4; i++) {
        h[i] = __bfloat162float(__float2bfloat16(w[i]));
        l[i] = w[i] - h[i];
    }
    g_Wfrag[r][kblk][nblk][lane] =
        make_uint4(pack_bf16(h[0], h[1]), pack_bf16(h[2], h[3]),
                   pack_bf16(l[0], l[1]), pack_bf16(l[2], l[3]));
}

static __device__ __forceinline__ uint32_t smem_u32(const void* p) {
    uint32_t a;
    asm("{ .reg .u64 t; cvta.to.shared.u64 t, %1; cvt.u32.u64 %0, t; }" : "=r"(a) : "l"(p));
    return a;
}

#define LDMATRIX_X4(fr, addr)                                              \
    asm volatile("ldmatrix.sync.aligned.m8n8.x4.shared.b16 "               \
                 "{%0, %1, %2, %3}, [%4];"                                 \
                 : "=r"((fr)[0]), "=r"((fr)[1]), "=r"((fr)[2]), "=r"((fr)[3]) \
                 : "r"(addr))

#define MMA_BF16(acc, a, b0, b1)                                           \
    asm volatile("mma.sync.aligned.m16n8k16.row.col.f32.bf16.bf16.f32 "    \
                 "{%0, %1, %2, %3}, {%4, %5, %6, %7}, {%8, %9}, "          \
                 "{%0, %1, %2, %3};"                                       \
                 : "+f"((acc)[0]), "+f"((acc)[1]), "+f"((acc)[2]), "+f"((acc)[3]) \
                 : "r"((a)[0]), "r"((a)[1]), "r"((a)[2]), "r"((a)[3]),     \
                   "r"(b0), "r"(b1))

__global__ __launch_bounds__(THREADS, 2)
void rgcn_hmma_kernel(const float* __restrict__ feat,
                      const int*   __restrict__ edge_src,
                      const int*   __restrict__ edge_dst,
                      float*       __restrict__ out,
                      int E)
{
    __shared__ __align__(1024) __nv_bfloat16 Ah[TE * D];   // 16KB, SW128-swizzled
    __shared__ __align__(1024) __nv_bfloat16 Al[TE * D];   // 16KB

    const int r   = blockIdx.y;
    const int e0  = blockIdx.x * TE;
    const int tid = threadIdx.x;
    const int wid = tid >> 5;
    const int lid = tid & 31;
    const int wm  = wid & 3;     // m 32-slice (edges)
    const int wn  = wid >> 2;    // n 32-slice (outputs)
    const int nE  = min(TE, E - e0);

    char* Ahb = reinterpret_cast<char*>(Ah);
    char* Alb = reinterpret_cast<char*>(Al);

    // ---- gather + bf16 hi/lo split into swizzled smem ----
    // 8 threads per edge; within one LDG.128 instruction, 8 consecutive lanes
    // cover one FULL 128B feature line of one edge -> 1 wavefront per line.
    {
        const int* srcp = edge_src + (size_t)r * E + e0;
        const int p = tid & 7;                 // float4 piece within line 0
        #pragma unroll
        for (int ep = 0; ep < 4; ep++) {
            const int e = (tid >> 3) + ep * 32;
            const uint32_t oa = SWZ((uint32_t)(e * 128 + p * 8));        // k = 4p..4p+3
            const uint32_t ob = SWZ((uint32_t)(e * 128 + 64 + p * 8));   // k = 32+4p..
            if (e < nE) {
                const int s = srcp[e];
                const float4* fr = reinterpret_cast<const float4*>(feat + (size_t)s * D);
                const float4 va = fr[p];       // line 0 of this edge's row
                const float4 vb = fr[p + 8];   // line 1

                float ha0 = __bfloat162float(__float2bfloat16(va.x));
                float ha1 = __bfloat162float(__float2bfloat16(va.y));
                float ha2 = __bfloat162float(__float2bfloat16(va.z));
                float ha3 = __bfloat162float(__float2bfloat16(va.w));
                float hb0 = __bfloat162float(__float2bfloat16(vb.x));
                float hb1 = __bfloat162float(__float2bfloat16(vb.y));
                float hb2 = __bfloat162float(__float2bfloat16(vb.z));
                float hb3 = __bfloat162float(__float2bfloat16(vb.w));

                *reinterpret_cast<uint2*>(Ahb + oa) =
                    make_uint2(pack_bf16(ha0, ha1), pack_bf16(ha2, ha3));
                *reinterpret_cast<uint2*>(Alb + oa) =
                    make_uint2(pack_bf16(va.x - ha0, va.y - ha1),
                               pack_bf16(va.z - ha2, va.w - ha3));
                *reinterpret_cast<uint2*>(Ahb + ob) =
                    make_uint2(pack_bf16(hb0, hb1), pack_bf16(hb2, hb3));
                *reinterpret_cast<uint2*>(Alb + ob) =
                    make_uint2(pack_bf16(vb.x - hb0, vb.y - hb1),
                               pack_bf16(vb.z - hb2, vb.w - hb3));
            } else {
                *reinterpret_cast<uint2*>(Ahb + oa) = make_uint2(0u, 0u);
                *reinterpret_cast<uint2*>(Alb + oa) = make_uint2(0u, 0u);
                *reinterpret_cast<uint2*>(Ahb + ob) = make_uint2(0u, 0u);
                *reinterpret_cast<uint2*>(Alb + ob) = make_uint2(0u, 0u);
            }
        }
    }
    __syncthreads();

    // ---- HMMA mainloop (round-3 tiling): acc[mt][nb][4], D = Ah*Bh + Al*Bh + Ah*Bl
    float acc[2][4][4];
    #pragma unroll
    for (int mt = 0; mt < 2; mt++)
        #pragma unroll
        for (int nb = 0; nb < 4; nb++)
            #pragma unroll
            for (int j = 0; j < 4; j++) acc[mt][nb][j] = 0.f;

    const uint32_t ah_base = smem_u32(Ah);
    const uint32_t al_base = smem_u32(Al);
    const int lrow = lid & 15;
    const int lkof = (lid >> 4) * 16;

    #pragma unroll
    for (int kblk = 0; kblk < 4; kblk++) {
        uint32_t afh[2][4], afl[2][4];
        #pragma unroll
        for (int mt = 0; mt < 2; mt++) {
            const int row = wm * 32 + mt * 16 + lrow;
            const uint32_t off = SWZ((uint32_t)(row * 128 + kblk * 32 + lkof));
            LDMATRIX_X4(afh[mt], ah_base + off);
            LDMATRIX_X4(afl[mt], al_base + off);
        }
        #pragma unroll
        for (int nb = 0; nb < 4; nb++) {
            const uint4 B = __ldg(&g_Wfrag[r][kblk][wn * 4 + nb][lid]);
            #pragma unroll
            for (int mt = 0; mt < 2; mt++) {
                MMA_BF16(acc[mt][nb], afh[mt], B.x, B.y);
                MMA_BF16(acc[mt][nb], afl[mt], B.x, B.y);
                MMA_BF16(acc[mt][nb], afh[mt], B.z, B.w);
            }
        }
    }

    // ---- scatter: pair-shuffle fragments into 16B runs, red.global.add.v4 ----
    const int g = lid >> 2;
    int  dn[4];
    bool ok[4];
    #pragma unroll
    for (int rg = 0; rg < 4; rg++) {                 // rg = mt*2 + rh
        const int el = wm * 32 + (rg >> 1) * 16 + (rg & 1) * 8 + g;
        ok[rg] = (el < nE);
        dn[rg] = ok[rg] ? edge_dst[(size_t)r * E + e0 + el] : 0;
    }

    const int  odd      = lid & 1;
    const int  colquad  = ((lid & 2) >> 1) * 4;      // 0 or 4 within n8 block

    #pragma unroll
    for (int mt = 0; mt < 2; mt++) {
        #pragma unroll
        for (int rh = 0; rh < 2; rh++) {
            const int rg = mt * 2 + rh;
            #pragma unroll
            for (int nbp = 0; nbp < 2; nbp++) {
                // even lane emits nb = nbp*2, odd emits nbp*2+1;
                // each sends the partner's nb, receives its missing half.
                const float s0 = odd ? acc[mt][nbp * 2][rh * 2]
                                     : acc[mt][nbp * 2 + 1][rh * 2];
                const float s1 = odd ? acc[mt][nbp * 2][rh * 2 + 1]
                                     : acc[mt][nbp * 2 + 1][rh * 2 + 1];
                const float m0 = odd ? acc[mt][nbp * 2 + 1][rh * 2]
                                     : acc[mt][nbp * 2][rh * 2];
                const float m1 = odd ? acc[mt][nbp * 2 + 1][rh * 2 + 1]
                                     : acc[mt][nbp * 2][rh * 2 + 1];
                const float r0 = __shfl_xor_sync(0xffffffffu, s0, 1);
                const float r1 = __shfl_xor_sync(0xffffffffu, s1, 1);

                // even lane owns lower t2 -> (mine, recv); odd -> (recv, mine)
                const float v0 = odd ? r0 : m0;
                const float v1 = odd ? r1 : m1;
                const float v2 = odd ? m0 : r0;
                const float v3 = odd ? m1 : r1;

                if (ok[rg]) {
                    const int col = wn * 32 + (nbp * 2 + odd) * 8 + colquad;
                    float* o = out + (size_t)dn[rg] * D + col;   // 16B aligned
                    asm volatile("red.global.add.v4.f32 [%0], {%1, %2, %3, %4};"
                                 :: "l"(o), "f"(v0), "f"(v1), "f"(v2), "f"(v3)
                                 : "memory");
                }
            }
        }
    }
}

extern "C" void kernel_launch(void* const* d_in, const int* in_sizes, int n_in,
                              void* d_out, int out_size)
{
    const float* feat     = (const float*)d_in[0];
    const float* weight   = (const float*)d_in[1];
    const int*   edge_src = (const int*)d_in[2];
    const int*   edge_dst = (const int*)d_in[3];
    float*       out      = (float*)d_out;

    const int R = in_sizes[1] / (D * D);     // 8
    const int E = in_sizes[2] / R;           // 100000

    cudaMemsetAsync(d_out, 0, (size_t)out_size * sizeof(float), 0);

    prep_w<<<R, 1024>>>(weight);

    dim3 grid((E + TE - 1) / TE, R);
    rgcn_hmma_kernel<<<grid, THREADS>>>(feat, edge_src, edge_dst, out, E);
}

// round 6
// speedup vs baseline: 1.2586x; 1.1812x over previous
#include <cuda_runtime.h>
#include <cuda_bf16.h>
#include <cstdint>

#define D        64
#define TE       128
#define THREADS  256

#define SWZ(o) ((o) ^ (((o) >> 3) & 0x70))

// Pre-split, per-lane-fragment-ordered weights: [r][kblk][nblk][lane] = {bh0,bh1,bl0,bl1}
__device__ uint4 g_Wfrag[8][4][8][32];

static __device__ __forceinline__ uint32_t pack_bf16(float lo, float hi) {
    __nv_bfloat162 v = __floats2bfloat162_rn(lo, hi);   // .x = lo (low 16 bits)
    return *reinterpret_cast<uint32_t*>(&v);
}

__global__ void prep_w(const float* __restrict__ W) {
    const int r    = blockIdx.x;
    const int t    = threadIdx.x;          // 1024 threads
    const int kblk = t >> 8;
    const int nblk = (t >> 5) & 7;
    const int lane = t & 31;

    const int n  = nblk * 8 + (lane >> 2);
    const int t2 = (lane & 3) * 2;
    const int k0 = kblk * 16;

    float w[4];
    w[0] = W[((size_t)r * D + k0 + t2    ) * D + n];
    w[1] = W[((size_t)r * D + k0 + t2 + 1) * D + n];
    w[2] = W[((size_t)r * D + k0 + t2 + 8) * D + n];
    w[3] = W[((size_t)r * D + k0 + t2 + 9) * D + n];

    float h[4], l[4];
    #pragma unroll
    for (int i = 0; i < 4; i++) {
        h[i] = __bfloat162float(__float2bfloat16(w[i]));
        l[i] = w[i] - h[i];
    }
    g_Wfrag[r][kblk][nblk][lane] =
        make_uint4(pack_bf16(h[0], h[1]), pack_bf16(h[2], h[3]),
                   pack_bf16(l[0], l[1]), pack_bf16(l[2], l[3]));
}

static __device__ __forceinline__ uint32_t smem_u32(const void* p) {
    uint32_t a;
    asm("{ .reg .u64 t; cvta.to.shared.u64 t, %1; cvt.u32.u64 %0, t; }" : "=r"(a) : "l"(p));
    return a;
}

#define LDMATRIX_X4(fr, addr)                                              \
    asm volatile("ldmatrix.sync.aligned.m8n8.x4.shared.b16 "               \
                 "{%0, %1, %2, %3}, [%4];"                                 \
                 : "=r"((fr)[0]), "=r"((fr)[1]), "=r"((fr)[2]), "=r"((fr)[3]) \
                 : "r"(addr))

#define MMA_BF16(acc, a, b0, b1)                                           \
    asm volatile("mma.sync.aligned.m16n8k16.row.col.f32.bf16.bf16.f32 "    \
                 "{%0, %1, %2, %3}, {%4, %5, %6, %7}, {%8, %9}, "          \
                 "{%0, %1, %2, %3};"                                       \
                 : "+f"((acc)[0]), "+f"((acc)[1]), "+f"((acc)[2]), "+f"((acc)[3]) \
                 : "r"((a)[0]), "r"((a)[1]), "r"((a)[2]), "r"((a)[3]),     \
                   "r"(b0), "r"(b1))

__global__ __launch_bounds__(THREADS, 3)
void rgcn_hmma_kernel(const float* __restrict__ feat,
                      const int*   __restrict__ edge_src,
                      const int*   __restrict__ edge_dst,
                      float*       __restrict__ out,
                      int E)
{
    __shared__ __align__(1024) __nv_bfloat16 Ah[TE * D];   // 16KB, SW128-swizzled
    __shared__ __align__(1024) __nv_bfloat16 Al[TE * D];   // 16KB

    const int r   = blockIdx.y;
    const int e0  = blockIdx.x * TE;
    const int tid = threadIdx.x;
    const int wid = tid >> 5;
    const int lid = tid & 31;
    const int wm  = wid & 3;     // m 32-slice (edges)
    const int wn  = wid >> 2;    // n 32-slice (outputs)
    const int nE  = min(TE, E - e0);

    char* Ahb = reinterpret_cast<char*>(Ah);
    char* Alb = reinterpret_cast<char*>(Al);

    // ---- prefetch scatter destinations early (independent LDGs) ----
    const int g = lid >> 2;
    int  dn[4];
    bool ok[4];
    #pragma unroll
    for (int rg = 0; rg < 4; rg++) {                 // rg = mt*2 + rh
        const int el = wm * 32 + (rg >> 1) * 16 + (rg & 1) * 8 + g;
        ok[rg] = (el < nE);
        dn[rg] = ok[rg] ? edge_dst[(size_t)r * E + e0 + el] : 0;
    }

    // ---- gather + bf16 hi/lo split into swizzled smem ----
    // 8 threads per edge; one LDG.128 instruction covers one full 128B line.
    // Indices prefetched; 2 edges (4 LDGs) in flight to bound register use.
    {
        const int* srcp = edge_src + (size_t)r * E + e0;
        const int p  = tid & 7;
        const int eb = tid >> 3;           // base edge 0..31
        int s[4];
        #pragma unroll
        for (int ep = 0; ep < 4; ep++) {
            const int e = eb + ep * 32;
            s[ep] = (e < nE) ? srcp[e] : -1;
        }
        #pragma unroll 2
        for (int ep = 0; ep < 4; ep++) {
            const int e = eb + ep * 32;
            const uint32_t oa = SWZ((uint32_t)(e * 128 + p * 8));        // k = 4p..4p+3
            const uint32_t ob = SWZ((uint32_t)(e * 128 + 64 + p * 8));   // k = 32+4p..
            if (s[ep] >= 0) {
                const float4* fr = reinterpret_cast<const float4*>(feat + (size_t)s[ep] * D);
                const float4 va = fr[p];
                const float4 vb = fr[p + 8];

                float ha0 = __bfloat162float(__float2bfloat16(va.x));
                float ha1 = __bfloat162float(__float2bfloat16(va.y));
                float ha2 = __bfloat162float(__float2bfloat16(va.z));
                float ha3 = __bfloat162float(__float2bfloat16(va.w));
                *reinterpret_cast<uint2*>(Ahb + oa) =
                    make_uint2(pack_bf16(ha0, ha1), pack_bf16(ha2, ha3));
                *reinterpret_cast<uint2*>(Alb + oa) =
                    make_uint2(pack_bf16(va.x - ha0, va.y - ha1),
                               pack_bf16(va.z - ha2, va.w - ha3));

                float hb0 = __bfloat162float(__float2bfloat16(vb.x));
                float hb1 = __bfloat162float(__float2bfloat16(vb.y));
                float hb2 = __bfloat162float(__float2bfloat16(vb.z));
                float hb3 = __bfloat162float(__float2bfloat16(vb.w));
                *reinterpret_cast<uint2*>(Ahb + ob) =
                    make_uint2(pack_bf16(hb0, hb1), pack_bf16(hb2, hb3));
                *reinterpret_cast<uint2*>(Alb + ob) =
                    make_uint2(pack_bf16(vb.x - hb0, vb.y - hb1),
                               pack_bf16(vb.z - hb2, vb.w - hb3));
            } else {
                *reinterpret_cast<uint2*>(Ahb + oa) = make_uint2(0u, 0u);
                *reinterpret_cast<uint2*>(Alb + oa) = make_uint2(0u, 0u);
                *reinterpret_cast<uint2*>(Ahb + ob) = make_uint2(0u, 0u);
                *reinterpret_cast<uint2*>(Alb + ob) = make_uint2(0u, 0u);
            }
        }
    }
    __syncthreads();

    // ---- HMMA mainloop (round-3 tiling): acc[mt][nb][4], D = Ah*Bh + Al*Bh + Ah*Bl
    float acc[2][4][4];
    #pragma unroll
    for (int mt = 0; mt < 2; mt++)
        #pragma unroll
        for (int nb = 0; nb < 4; nb++)
            #pragma unroll
            for (int j = 0; j < 4; j++) acc[mt][nb][j] = 0.f;

    const uint32_t ah_base = smem_u32(Ah);
    const uint32_t al_base = smem_u32(Al);
    const int lrow = lid & 15;
    const int lkof = (lid >> 4) * 16;

    #pragma unroll
    for (int kblk = 0; kblk < 4; kblk++) {
        uint32_t afh[2][4], afl[2][4];
        #pragma unroll
        for (int mt = 0; mt < 2; mt++) {
            const int row = wm * 32 + mt * 16 + lrow;
            const uint32_t off = SWZ((uint32_t)(row * 128 + kblk * 32 + lkof));
            LDMATRIX_X4(afh[mt], ah_base + off);
            LDMATRIX_X4(afl[mt], al_base + off);
        }
        #pragma unroll
        for (int nb = 0; nb < 4; nb++) {
            const uint4 B = __ldg(&g_Wfrag[r][kblk][wn * 4 + nb][lid]);
            #pragma unroll
            for (int mt = 0; mt < 2; mt++) {
                MMA_BF16(acc[mt][nb], afh[mt], B.x, B.y);
                MMA_BF16(acc[mt][nb], afl[mt], B.x, B.y);
                MMA_BF16(acc[mt][nb], afh[mt], B.z, B.w);
            }
        }
    }

    // ---- scatter: pair-shuffle fragments into 16B runs, red.global.add.v4 ----
    const int  odd      = lid & 1;
    const int  colquad  = ((lid & 2) >> 1) * 4;      // 0 or 4 within n8 block

    #pragma unroll
    for (int mt = 0; mt < 2; mt++) {
        #pragma unroll
        for (int rh = 0; rh < 2; rh++) {
            const int rg = mt * 2 + rh;
            #pragma unroll
            for (int nbp = 0; nbp < 2; nbp++) {
                // even lane emits nb = nbp*2, odd emits nbp*2+1;
                // each sends the partner's nb, receives its missing half.
                const float s0 = odd ? acc[mt][nbp * 2][rh * 2]
                                     : acc[mt][nbp * 2 + 1][rh * 2];
                const float s1 = odd ? acc[mt][nbp * 2][rh * 2 + 1]
                                     : acc[mt][nbp * 2 + 1][rh * 2 + 1];
                const float m0 = odd ? acc[mt][nbp * 2 + 1][rh * 2]
                                     : acc[mt][nbp * 2][rh * 2];
                const float m1 = odd ? acc[mt][nbp * 2 + 1][rh * 2 + 1]
                                     : acc[mt][nbp * 2][rh * 2 + 1];
                const float r0 = __shfl_xor_sync(0xffffffffu, s0, 1);
                const float r1 = __shfl_xor_sync(0xffffffffu, s1, 1);

                // even lane owns lower t2 -> (mine, recv); odd -> (recv, mine)
                const float v0 = odd ? r0 : m0;
                const float v1 = odd ? r1 : m1;
                const float v2 = odd ? m0 : r0;
                const float v3 = odd ? m1 : r1;

                if (ok[rg]) {
                    const int col = wn * 32 + (nbp * 2 + odd) * 8 + colquad;
                    float* o = out + (size_t)dn[rg] * D + col;   // 16B aligned
                    asm volatile("red.global.add.v4.f32 [%0], {%1, %2, %3, %4};"
                                 :: "l"(o), "f"(v0), "f"(v1), "f"(v2), "f"(v3)
                                 : "memory");
                }
            }
        }
    }
}

extern "C" void kernel_launch(void* const* d_in, const int* in_sizes, int n_in,
                              void* d_out, int out_size)
{
    const float* feat     = (const float*)d_in[0];
    const float* weight   = (const float*)d_in[1];
    const int*   edge_src = (const int*)d_in[2];
    const int*   edge_dst = (const int*)d_in[3];
    float*       out      = (float*)d_out;

    const int R = in_sizes[1] / (D * D);     // 8
    const int E = in_sizes[2] / R;           // 100000

    cudaMemsetAsync(d_out, 0, (size_t)out_size * sizeof(float), 0);

    prep_w<<<R, 1024>>>(weight);

    dim3 grid((E + TE - 1) / TE, R);
    rgcn_hmma_kernel<<<grid, THREADS>>>(feat, edge_src, edge_dst, out, E);
}

// round 7
// speedup vs baseline: 1.2627x; 1.0033x over previous
#include <cuda_runtime.h>
#include <cuda_bf16.h>
#include <cstdint>

#define D        64
#define TE       128
#define THREADS  256

#define SWZ(o) ((o) ^ (((o) >> 3) & 0x70))

// Pre-split, per-lane-fragment-ordered weights: [r][kblk][nblk][lane] = {bh0,bh1,bl0,bl1}
__device__ uint4 g_Wfrag[8][4][8][32];

static __device__ __forceinline__ uint32_t pack_bf16(float lo, float hi) {
    __nv_bfloat162 v = __floats2bfloat162_rn(lo, hi);   // .x = lo (low 16 bits)
    return *reinterpret_cast<uint32_t*>(&v);
}

// Fused: blocks [0, R) build W fragments; blocks [R, ...) zero the output.
__global__ void prep_and_zero(const float* __restrict__ W, float4* __restrict__ outv,
                              int n4, int R)
{
    if (blockIdx.x < (unsigned)R) {
        const int r = blockIdx.x;
        const int t = threadIdx.x;             // 256 threads
        const int nblk = (t >> 5) & 7;
        const int lane = t & 31;
        const int n  = nblk * 8 + (lane >> 2);
        const int t2 = (lane & 3) * 2;
        for (int kblk = 0; kblk < 4; kblk++) {
            const int k0 = kblk * 16;
            float w[4];
            w[0] = W[((size_t)r * D + k0 + t2    ) * D + n];
            w[1] = W[((size_t)r * D + k0 + t2 + 1) * D + n];
            w[2] = W[((size_t)r * D + k0 + t2 + 8) * D + n];
            w[3] = W[((size_t)r * D + k0 + t2 + 9) * D + n];
            float h[4], l[4];
            #pragma unroll
            for (int i = 0; i < 4; i++) {
                h[i] = __bfloat162float(__float2bfloat16(w[i]));
                l[i] = w[i] - h[i];
            }
            g_Wfrag[r][kblk][nblk][lane] =
                make_uint4(pack_bf16(h[0], h[1]), pack_bf16(h[2], h[3]),
                           pack_bf16(l[0], l[1]), pack_bf16(l[2], l[3]));
        }
    } else {
        const int nzb = gridDim.x - R;
        const float4 z = make_float4(0.f, 0.f, 0.f, 0.f);
        for (int i = (blockIdx.x - R) * THREADS + threadIdx.x; i < n4;
             i += nzb * THREADS)
            outv[i] = z;
    }
}

static __device__ __forceinline__ uint32_t smem_u32(const void* p) {
    uint32_t a;
    asm("{ .reg .u64 t; cvta.to.shared.u64 t, %1; cvt.u32.u64 %0, t; }" : "=r"(a) : "l"(p));
    return a;
}

#define LDMATRIX_X4(fr, addr)                                              \
    asm volatile("ldmatrix.sync.aligned.m8n8.x4.shared.b16 "               \
                 "{%0, %1, %2, %3}, [%4];"                                 \
                 : "=r"((fr)[0]), "=r"((fr)[1]), "=r"((fr)[2]), "=r"((fr)[3]) \
                 : "r"(addr))

#define MMA_BF16(acc, a, b0, b1)                                           \
    asm volatile("mma.sync.aligned.m16n8k16.row.col.f32.bf16.bf16.f32 "    \
                 "{%0, %1, %2, %3}, {%4, %5, %6, %7}, {%8, %9}, "          \
                 "{%0, %1, %2, %3};"                                       \
                 : "+f"((acc)[0]), "+f"((acc)[1]), "+f"((acc)[2]), "+f"((acc)[3]) \
                 : "r"((a)[0]), "r"((a)[1]), "r"((a)[2]), "r"((a)[3]),     \
                   "r"(b0), "r"(b1))

__global__ __launch_bounds__(THREADS, 4)
void rgcn_hmma_kernel(const float* __restrict__ feat,
                      const int*   __restrict__ edge_src,
                      const int*   __restrict__ edge_dst,
                      float*       __restrict__ out,
                      int E)
{
    __shared__ __align__(1024) __nv_bfloat16 Ah[TE * D];   // 16KB, SW128-swizzled
    __shared__ __align__(1024) __nv_bfloat16 Al[TE * D];   // 16KB

    const int r   = blockIdx.y;
    const int e0  = blockIdx.x * TE;
    const int tid = threadIdx.x;
    const int wid = tid >> 5;
    const int lid = tid & 31;
    const int wm  = wid & 3;     // m 32-slice (edges)
    const int wn  = wid >> 2;    // n 32-slice (outputs)
    const int nE  = min(TE, E - e0);

    char* Ahb = reinterpret_cast<char*>(Ah);
    char* Alb = reinterpret_cast<char*>(Al);

    // ---- gather + bf16 hi/lo split into swizzled smem ----
    // 8 threads per edge; one LDG.128 instruction covers one full 128B line.
    {
        const int* srcp = edge_src + (size_t)r * E + e0;
        const int p  = tid & 7;
        const int eb = tid >> 3;           // base edge 0..31
        int s[4];
        #pragma unroll
        for (int ep = 0; ep < 4; ep++) {
            const int e = eb + ep * 32;
            s[ep] = (e < nE) ? srcp[e] : -1;
        }
        #pragma unroll 2
        for (int ep = 0; ep < 4; ep++) {
            const int e = eb + ep * 32;
            const uint32_t oa = SWZ((uint32_t)(e * 128 + p * 8));        // k = 4p..4p+3
            const uint32_t ob = SWZ((uint32_t)(e * 128 + 64 + p * 8));   // k = 32+4p..
            if (s[ep] >= 0) {
                const float4* fr = reinterpret_cast<const float4*>(feat + (size_t)s[ep] * D);
                const float4 va = fr[p];
                const float4 vb = fr[p + 8];

                float ha0 = __bfloat162float(__float2bfloat16(va.x));
                float ha1 = __bfloat162float(__float2bfloat16(va.y));
                float ha2 = __bfloat162float(__float2bfloat16(va.z));
                float ha3 = __bfloat162float(__float2bfloat16(va.w));
                *reinterpret_cast<uint2*>(Ahb + oa) =
                    make_uint2(pack_bf16(ha0, ha1), pack_bf16(ha2, ha3));
                *reinterpret_cast<uint2*>(Alb + oa) =
                    make_uint2(pack_bf16(va.x - ha0, va.y - ha1),
                               pack_bf16(va.z - ha2, va.w - ha3));

                float hb0 = __bfloat162float(__float2bfloat16(vb.x));
                float hb1 = __bfloat162float(__float2bfloat16(vb.y));
                float hb2 = __bfloat162float(__float2bfloat16(vb.z));
                float hb3 = __bfloat162float(__float2bfloat16(vb.w));
                *reinterpret_cast<uint2*>(Ahb + ob) =
                    make_uint2(pack_bf16(hb0, hb1), pack_bf16(hb2, hb3));
                *reinterpret_cast<uint2*>(Alb + ob) =
                    make_uint2(pack_bf16(vb.x - hb0, vb.y - hb1),
                               pack_bf16(vb.z - hb2, vb.w - hb3));
            } else {
                *reinterpret_cast<uint2*>(Ahb + oa) = make_uint2(0u, 0u);
                *reinterpret_cast<uint2*>(Alb + oa) = make_uint2(0u, 0u);
                *reinterpret_cast<uint2*>(Ahb + ob) = make_uint2(0u, 0u);
                *reinterpret_cast<uint2*>(Alb + ob) = make_uint2(0u, 0u);
            }
        }
    }
    __syncthreads();

    // ---- HMMA mainloop (round-3 tiling): acc[mt][nb][4], D = Ah*Bh + Al*Bh + Ah*Bl
    float acc[2][4][4];
    #pragma unroll
    for (int mt = 0; mt < 2; mt++)
        #pragma unroll
        for (int nb = 0; nb < 4; nb++)
            #pragma unroll
            for (int j = 0; j < 4; j++) acc[mt][nb][j] = 0.f;

    const uint32_t ah_base = smem_u32(Ah);
    const uint32_t al_base = smem_u32(Al);
    const int lrow = lid & 15;
    const int lkof = (lid >> 4) * 16;

    #pragma unroll
    for (int kblk = 0; kblk < 4; kblk++) {
        uint32_t afh[2][4], afl[2][4];
        #pragma unroll
        for (int mt = 0; mt < 2; mt++) {
            const int row = wm * 32 + mt * 16 + lrow;
            const uint32_t off = SWZ((uint32_t)(row * 128 + kblk * 32 + lkof));
            LDMATRIX_X4(afh[mt], ah_base + off);
            LDMATRIX_X4(afl[mt], al_base + off);
        }
        #pragma unroll
        for (int nb = 0; nb < 4; nb++) {
            const uint4 B = __ldg(&g_Wfrag[r][kblk][wn * 4 + nb][lid]);
            #pragma unroll
            for (int mt = 0; mt < 2; mt++) {
                MMA_BF16(acc[mt][nb], afh[mt], B.x, B.y);
                MMA_BF16(acc[mt][nb], afl[mt], B.x, B.y);
                MMA_BF16(acc[mt][nb], afh[mt], B.z, B.w);
            }
        }
    }

    // ---- scatter destinations (loaded late: 32 warps/SM hide this latency) ----
    const int g = lid >> 2;
    int  dn[4];
    bool ok[4];
    #pragma unroll
    for (int rg = 0; rg < 4; rg++) {                 // rg = mt*2 + rh
        const int el = wm * 32 + (rg >> 1) * 16 + (rg & 1) * 8 + g;
        ok[rg] = (el < nE);
        dn[rg] = ok[rg] ? edge_dst[(size_t)r * E + e0 + el] : 0;
    }

    // ---- scatter: pair-shuffle fragments into 16B runs, red.global.add.v4 ----
    const int  odd      = lid & 1;
    const int  colquad  = ((lid & 2) >> 1) * 4;      // 0 or 4 within n8 block

    #pragma unroll
    for (int mt = 0; mt < 2; mt++) {
        #pragma unroll
        for (int rh = 0; rh < 2; rh++) {
            const int rg = mt * 2 + rh;
            #pragma unroll
            for (int nbp = 0; nbp < 2; nbp++) {
                // even lane emits nb = nbp*2, odd emits nbp*2+1;
                // each sends the partner's nb, receives its missing half.
                const float s0 = odd ? acc[mt][nbp * 2][rh * 2]
                                     : acc[mt][nbp * 2 + 1][rh * 2];
                const float s1 = odd ? acc[mt][nbp * 2][rh * 2 + 1]
                                     : acc[mt][nbp * 2 + 1][rh * 2 + 1];
                const float m0 = odd ? acc[mt][nbp * 2 + 1][rh * 2]
                                     : acc[mt][nbp * 2][rh * 2];
                const float m1 = odd ? acc[mt][nbp * 2 + 1][rh * 2 + 1]
                                     : acc[mt][nbp * 2][rh * 2 + 1];
                const float r0 = __shfl_xor_sync(0xffffffffu, s0, 1);
                const float r1 = __shfl_xor_sync(0xffffffffu, s1, 1);

                // even lane owns lower t2 -> (mine, recv); odd -> (recv, mine)
                const float v0 = odd ? r0 : m0;
                const float v1 = odd ? r1 : m1;
                const float v2 = odd ? m0 : r0;
                const float v3 = odd ? m1 : r1;

                if (ok[rg]) {
                    const int col = wn * 32 + (nbp * 2 + odd) * 8 + colquad;
                    float* o = out + (size_t)dn[rg] * D + col;   // 16B aligned
                    asm volatile("red.global.add.v4.f32 [%0], {%1, %2, %3, %4};"
                                 :: "l"(o), "f"(v0), "f"(v1), "f"(v2), "f"(v3)
                                 : "memory");
                }
            }
        }
    }
}

extern "C" void kernel_launch(void* const* d_in, const int* in_sizes, int n_in,
                              void* d_out, int out_size)
{
    const float* feat     = (const float*)d_in[0];
    const float* weight   = (const float*)d_in[1];
    const int*   edge_src = (const int*)d_in[2];
    const int*   edge_dst = (const int*)d_in[3];
    float*       out      = (float*)d_out;

    const int R = in_sizes[1] / (D * D);     // 8
    const int E = in_sizes[2] / R;           // 100000

    // fused W-prep + output zeroing (out_size is a multiple of 4 floats)
    prep_and_zero<<<R + 2048, THREADS>>>(weight, (float4*)d_out, out_size / 4, R);

    dim3 grid((E + TE - 1) / TE, R);
    rgcn_hmma_kernel<<<grid, THREADS>>>(feat, edge_src, edge_dst, out, E);
}

// round 10
// speedup vs baseline: 1.2922x; 1.0233x over previous
#include <cuda_runtime.h>
#include <cuda_bf16.h>
#include <cstdint>

#define D        64
#define TE       128
#define THREADS  256

#define SWZ(o) ((o) ^ (((o) >> 3) & 0x70))

// Pre-split, per-lane-fragment-ordered weights: [r][kblk][nblk][lane] = {bh0,bh1,bl0,bl1}
__device__ uint4 g_Wfrag[8][4][8][32];

static __device__ __forceinline__ uint32_t pack_bf16(float lo, float hi) {
    __nv_bfloat162 v = __floats2bfloat162_rn(lo, hi);   // .x = lo (low 16 bits)
    return *reinterpret_cast<uint32_t*>(&v);
}

// Fused: blocks [0, R) build W fragments; blocks [R, ...) zero the output.
__global__ void prep_and_zero(const float* __restrict__ W, float4* __restrict__ outv,
                              int n4, int R)
{
    if (blockIdx.x < (unsigned)R) {
        const int r = blockIdx.x;
        const int t = threadIdx.x;             // 256 threads
        const int nblk = (t >> 5) & 7;
        const int lane = t & 31;
        const int n  = nblk * 8 + (lane >> 2);
        const int t2 = (lane & 3) * 2;
        for (int kblk = 0; kblk < 4; kblk++) {
            const int k0 = kblk * 16;
            float w[4];
            w[0] = W[((size_t)r * D + k0 + t2    ) * D + n];
            w[1] = W[((size_t)r * D + k0 + t2 + 1) * D + n];
            w[2] = W[((size_t)r * D + k0 + t2 + 8) * D + n];
            w[3] = W[((size_t)r * D + k0 + t2 + 9) * D + n];
            float h[4], l[4];
            #pragma unroll
            for (int i = 0; i < 4; i++) {
                h[i] = __bfloat162float(__float2bfloat16(w[i]));
                l[i] = w[i] - h[i];
            }
            g_Wfrag[r][kblk][nblk][lane] =
                make_uint4(pack_bf16(h[0], h[1]), pack_bf16(h[2], h[3]),
                           pack_bf16(l[0], l[1]), pack_bf16(l[2], l[3]));
        }
    } else {
        const int nzb = gridDim.x - R;
        const float4 z = make_float4(0.f, 0.f, 0.f, 0.f);
        for (int i = (blockIdx.x - R) * THREADS + threadIdx.x; i < n4;
             i += nzb * THREADS)
            outv[i] = z;
    }
}

static __device__ __forceinline__ uint32_t smem_u32(const void* p) {
    uint32_t a;
    asm("{ .reg .u64 t; cvta.to.shared.u64 t, %1; cvt.u32.u64 %0, t; }" : "=r"(a) : "l"(p));
    return a;
}

#define LDMATRIX_X4(fr, addr)                                              \
    asm volatile("ldmatrix.sync.aligned.m8n8.x4.shared.b16 "               \
                 "{%0, %1, %2, %3}, [%4];"                                 \
                 : "=r"((fr)[0]), "=r"((fr)[1]), "=r"((fr)[2]), "=r"((fr)[3]) \
                 : "r"(addr))

#define MMA_BF16(acc, a, b0, b1)                                           \
    asm volatile("mma.sync.aligned.m16n8k16.row.col.f32.bf16.bf16.f32 "    \
                 "{%0, %1, %2, %3}, {%4, %5, %6, %7}, {%8, %9}, "          \
                 "{%0, %1, %2, %3};"                                       \
                 : "+f"((acc)[0]), "+f"((acc)[1]), "+f"((acc)[2]), "+f"((acc)[3]) \
                 : "r"((a)[0]), "r"((a)[1]), "r"((a)[2]), "r"((a)[3]),     \
                   "r"(b0), "r"(b1))

__global__ __launch_bounds__(THREADS, 3)
void rgcn_hmma_kernel(const float* __restrict__ feat,
                      const int*   __restrict__ edge_src,
                      const int*   __restrict__ edge_dst,
                      float*       __restrict__ out,
                      int E)
{
    __shared__ __align__(1024) __nv_bfloat16 Ah[TE * D];   // 16KB, SW128-swizzled
    __shared__ __align__(1024) __nv_bfloat16 Al[TE * D];   // 16KB

    const int r   = blockIdx.y;
    const int e0  = blockIdx.x * TE;
    const int tid = threadIdx.x;
    const int wid = tid >> 5;
    const int lid = tid & 31;
    const int wm  = wid & 3;     // m 32-slice (edges)
    const int wn  = wid >> 2;    // n 32-slice (outputs)
    const int nE  = min(TE, E - e0);

    char* Ahb = reinterpret_cast<char*>(Ah);
    char* Alb = reinterpret_cast<char*>(Al);

    // ---- prefetch scatter destinations early (independent LDGs) ----
    const int g = lid >> 2;
    int  dn[4];
    bool ok[4];
    #pragma unroll
    for (int rg = 0; rg < 4; rg++) {                 // rg = mt*2 + rh
        const int el = wm * 32 + (rg >> 1) * 16 + (rg & 1) * 8 + g;
        ok[rg] = (el < nE);
        dn[rg] = ok[rg] ? edge_dst[(size_t)r * E + e0 + el] : 0;
    }

    // ---- gather + bf16 hi/lo split into swizzled smem ----
    // 8 threads per edge; one LDG.128 instruction covers one full 128B line.
    // Indices prefetched; 2 edges (4 LDGs) in flight to bound register use.
    {
        const int* srcp = edge_src + (size_t)r * E + e0;
        const int p  = tid & 7;
        const int eb = tid >> 3;           // base edge 0..31
        int s[4];
        #pragma unroll
        for (int ep = 0; ep < 4; ep++) {
            const int e = eb + ep * 32;
            s[ep] = (e < nE) ? srcp[e] : -1;
        }
        #pragma unroll 2
        for (int ep = 0; ep < 4; ep++) {
            const int e = eb + ep * 32;
            const uint32_t oa = SWZ((uint32_t)(e * 128 + p * 8));        // k = 4p..4p+3
            const uint32_t ob = SWZ((uint32_t)(e * 128 + 64 + p * 8));   // k = 32+4p..
            if (s[ep] >= 0) {
                const float4* fr = reinterpret_cast<const float4*>(feat + (size_t)s[ep] * D);
                const float4 va = fr[p];
                const float4 vb = fr[p + 8];

                float ha0 = __bfloat162float(__float2bfloat16(va.x));
                float ha1 = __bfloat162float(__float2bfloat16(va.y));
                float ha2 = __bfloat162float(__float2bfloat16(va.z));
                float ha3 = __bfloat162float(__float2bfloat16(va.w));
                *reinterpret_cast<uint2*>(Ahb + oa) =
                    make_uint2(pack_bf16(ha0, ha1), pack_bf16(ha2, ha3));
                *reinterpret_cast<uint2*>(Alb + oa) =
                    make_uint2(pack_bf16(va.x - ha0, va.y - ha1),
                               pack_bf16(va.z - ha2, va.w - ha3));

                float hb0 = __bfloat162float(__float2bfloat16(vb.x));
                float hb1 = __bfloat162float(__float2bfloat16(vb.y));
                float hb2 = __bfloat162float(__float2bfloat16(vb.z));
                float hb3 = __bfloat162float(__float2bfloat16(vb.w));
                *reinterpret_cast<uint2*>(Ahb + ob) =
                    make_uint2(pack_bf16(hb0, hb1), pack_bf16(hb2, hb3));
                *reinterpret_cast<uint2*>(Alb + ob) =
                    make_uint2(pack_bf16(vb.x - hb0, vb.y - hb1),
                               pack_bf16(vb.z - hb2, vb.w - hb3));
            } else {
                *reinterpret_cast<uint2*>(Ahb + oa) = make_uint2(0u, 0u);
                *reinterpret_cast<uint2*>(Alb + oa) = make_uint2(0u, 0u);
                *reinterpret_cast<uint2*>(Ahb + ob) = make_uint2(0u, 0u);
                *reinterpret_cast<uint2*>(Alb + ob) = make_uint2(0u, 0u);
            }
        }
    }
    __syncthreads();

    // ---- HMMA mainloop (round-3 tiling): acc[mt][nb][4], D = Ah*Bh + Al*Bh + Ah*Bl
    float acc[2][4][4];
    #pragma unroll
    for (int mt = 0; mt < 2; mt++)
        #pragma unroll
        for (int nb = 0; nb < 4; nb++)
            #pragma unroll
            for (int j = 0; j < 4; j++) acc[mt][nb][j] = 0.f;

    const uint32_t ah_base = smem_u32(Ah);
    const uint32_t al_base = smem_u32(Al);
    const int lrow = lid & 15;
    const int lkof = (lid >> 4) * 16;

    #pragma unroll
    for (int kblk = 0; kblk < 4; kblk++) {
        uint32_t afh[2][4], afl[2][4];
        #pragma unroll
        for (int mt = 0; mt < 2; mt++) {
            const int row = wm * 32 + mt * 16 + lrow;
            const uint32_t off = SWZ((uint32_t)(row * 128 + kblk * 32 + lkof));
            LDMATRIX_X4(afh[mt], ah_base + off);
            LDMATRIX_X4(afl[mt], al_base + off);
        }
        #pragma unroll
        for (int nb = 0; nb < 4; nb++) {
            const uint4 B = __ldg(&g_Wfrag[r][kblk][wn * 4 + nb][lid]);
            #pragma unroll
            for (int mt = 0; mt < 2; mt++) {
                MMA_BF16(acc[mt][nb], afh[mt], B.x, B.y);
                MMA_BF16(acc[mt][nb], afl[mt], B.x, B.y);
                MMA_BF16(acc[mt][nb], afh[mt], B.z, B.w);
            }
        }
    }

    // ---- scatter: pair-shuffle fragments into 16B runs, red.global.add.v4 ----
    const int  odd      = lid & 1;
    const int  colquad  = ((lid & 2) >> 1) * 4;      // 0 or 4 within n8 block

    #pragma unroll
    for (int mt = 0; mt < 2; mt++) {
        #pragma unroll
        for (int rh = 0; rh < 2; rh++) {
            const int rg = mt * 2 + rh;
            #pragma unroll
            for (int nbp = 0; nbp < 2; nbp++) {
                // even lane emits nb = nbp*2, odd emits nbp*2+1;
                // each sends the partner's nb, receives its missing half.
                const float s0 = odd ? acc[mt][nbp * 2][rh * 2]
                                     : acc[mt][nbp * 2 + 1][rh * 2];
                const float s1 = odd ? acc[mt][nbp * 2][rh * 2 + 1]
                                     : acc[mt][nbp * 2 + 1][rh * 2 + 1];
                const float m0 = odd ? acc[mt][nbp * 2 + 1][rh * 2]
                                     : acc[mt][nbp * 2][rh * 2];
                const float m1 = odd ? acc[mt][nbp * 2 + 1][rh * 2 + 1]
                                     : acc[mt][nbp * 2][rh * 2 + 1];
                const float r0 = __shfl_xor_sync(0xffffffffu, s0, 1);
                const float r1 = __shfl_xor_sync(0xffffffffu, s1, 1);

                // even lane owns lower t2 -> (mine, recv); odd -> (recv, mine)
                const float v0 = odd ? r0 : m0;
                const float v1 = odd ? r1 : m1;
                const float v2 = odd ? m0 : r0;
                const float v3 = odd ? m1 : r1;

                if (ok[rg]) {
                    const int col = wn * 32 + (nbp * 2 + odd) * 8 + colquad;
                    float* o = out + (size_t)dn[rg] * D + col;   // 16B aligned
                    asm volatile("red.global.add.v4.f32 [%0], {%1, %2, %3, %4};"
                                 :: "l"(o), "f"(v0), "f"(v1), "f"(v2), "f"(v3)
                                 : "memory");
                }
            }
        }
    }
}

extern "C" void kernel_launch(void* const* d_in, const int* in_sizes, int n_in,
                              void* d_out, int out_size)
{
    const float* feat     = (const float*)d_in[0];
    const float* weight   = (const float*)d_in[1];
    const int*   edge_src = (const int*)d_in[2];
    const int*   edge_dst = (const int*)d_in[3];
    float*       out      = (float*)d_out;

    const int R = in_sizes[1] / (D * D);     // 8
    const int E = in_sizes[2] / R;           // 100000

    // fused W-prep + output zeroing (out_size is a multiple of 4 floats)
    prep_and_zero<<<R + 2048, THREADS>>>(weight, (float4*)d_out, out_size / 4, R);

    dim3 grid((E + TE - 1) / TE, R);
    rgcn_hmma_kernel<<<grid, THREADS>>>(feat, edge_src, edge_dst, out, E);
}